// round 1
// baseline (speedup 1.0000x reference)
#include <cuda_runtime.h>

#define N_USERS 100000
#define N_ITEMS 50000
#define N_TOTAL (N_USERS + N_ITEMS)
#define D 64
#define D4 (D / 4)          // 16 float4 per row
#define HYPER_X 0.5f

// Scratch: e0 (input concat), e1, e2, e3 (per-layer SpMM outputs). 4 x 38.4MB.
__device__ float g_e0[N_TOTAL * D];
__device__ float g_e1[N_TOTAL * D];
__device__ float g_e2[N_TOTAL * D];
__device__ float g_e3[N_TOTAL * D];

// ---------------------------------------------------------------------------
// init: e0 = concat(emb_user, emb_item); e1=e2=e3=0
// ---------------------------------------------------------------------------
__global__ void init_kernel(const float4* __restrict__ eu,
                            const float4* __restrict__ ei) {
    const int total = N_TOTAL * D4;
    float4* b0 = reinterpret_cast<float4*>(g_e0);
    float4* b1 = reinterpret_cast<float4*>(g_e1);
    float4* b2 = reinterpret_cast<float4*>(g_e2);
    float4* b3 = reinterpret_cast<float4*>(g_e3);
    const float4 z = make_float4(0.f, 0.f, 0.f, 0.f);
    for (int i = blockIdx.x * blockDim.x + threadIdx.x; i < total;
         i += gridDim.x * blockDim.x) {
        float4 v = (i < N_USERS * D4) ? eu[i] : ei[i - N_USERS * D4];
        b0[i] = v;
        b1[i] = z;
        b2[i] = z;
        b3[i] = z;
    }
}

// ---------------------------------------------------------------------------
// SpMM: y[row] += val * x[col]   (y assumed pre-zeroed)
// One warp handles 2 edges: 16 lanes/edge, one float4 per lane.
// Edge metadata loaded once per 16-lane group, broadcast via shuffle.
// Scatter-add via vectorized red.global.add.v4.f32 (no return traffic).
// ---------------------------------------------------------------------------
__global__ void spmm_kernel(const float4* __restrict__ x,
                            float* __restrict__ y,
                            const int* __restrict__ row,
                            const int* __restrict__ col,
                            const float* __restrict__ val,
                            int nnz) {
    const int lane = threadIdx.x & 31;
    const int sub  = lane >> 4;      // which edge of the pair
    const int q    = lane & 15;      // float4 index within row
    const long warp_g = ((long)blockIdx.x * blockDim.x + threadIdx.x) >> 5;
    const long e = warp_g * 2 + sub;

    int r = 0, c = 0;
    float v = 0.f;
    if (q == 0 && e < nnz) {
        r = row[e];
        c = col[e];
        v = val[e];
    }
    r = __shfl_sync(0xffffffffu, r, sub * 16);
    c = __shfl_sync(0xffffffffu, c, sub * 16);
    v = __shfl_sync(0xffffffffu, v, sub * 16);

    if (e < nnz) {
        float4 xv = __ldg(&x[(long)c * D4 + q]);
        float px = v * xv.x, py = v * xv.y, pz = v * xv.z, pw = v * xv.w;
        float* addr = y + (long)r * D + q * 4;
        asm volatile("red.global.add.v4.f32 [%0], {%1, %2, %3, %4};"
                     :: "l"(addr), "f"(px), "f"(py), "f"(pz), "f"(pw)
                     : "memory");
    }
}

// ---------------------------------------------------------------------------
// Epilogue: per sample b,
//   u = (e0+e1+e2+e3)[users[b]] / 4 ;  i = (e0+e1+e2+e3)[N_USERS+items[b]] / 4
//   ue = u @ Wu^T ; ie = i @ Wi^T
//   out = 0.5 * sum_d softmax(ue)_d * sigmoid(ie_d) + 0.5 * sigmoid(xij_emb)
// 32 threads / sample; 8 samples / 256-thread block.
// ---------------------------------------------------------------------------
#define SAMPLES_PER_BLOCK 8

__device__ __forceinline__ float sigmoidf_(float x) {
    return 1.0f / (1.0f + expf(-x));
}

__global__ void epilogue_kernel(const float* __restrict__ w_user,
                                const float* __restrict__ w_item,
                                const float* __restrict__ xij_emb1,
                                const float* __restrict__ xij_emb0,
                                const int* __restrict__ users,
                                const int* __restrict__ items,
                                const int* __restrict__ xij,
                                float* __restrict__ out,
                                int B) {
    __shared__ float ws_u[D * D];                 // transposed: ws_u[k*64+d]
    __shared__ float ws_i[D * D];
    __shared__ float su[SAMPLES_PER_BLOCK][D];
    __shared__ float si[SAMPLES_PER_BLOCK][D];

    const int tid = threadIdx.x;
    // stage weights transposed (conflict-free consumption)
    for (int idx = tid; idx < D * D; idx += blockDim.x) {
        int d = idx >> 6, k = idx & 63;
        ws_u[k * D + d] = w_user[idx];
        ws_i[k * D + d] = w_item[idx];
    }

    const int w    = tid >> 5;                    // sample slot in block
    const int lane = tid & 31;
    const int s    = blockIdx.x * SAMPLES_PER_BLOCK + w;

    int item = 0, urow = 0, irow = 0;
    if (s < B) {
        urow = users[s];
        item = items[s];
        irow = N_USERS + item;
        // gather + layer-sum the two feature vectors (2 elems per lane)
        #pragma unroll
        for (int t = 0; t < 2; t++) {
            int j = lane + t * 32;
            long uo = (long)urow * D + j;
            long io = (long)irow * D + j;
            su[w][j] = 0.25f * (g_e0[uo] + g_e1[uo] + g_e2[uo] + g_e3[uo]);
            si[w][j] = 0.25f * (g_e0[io] + g_e1[io] + g_e2[io] + g_e3[io]);
        }
    }
    __syncthreads();
    if (s >= B) return;

    // two GEMV rows per lane for each matrix
    float au0 = 0.f, au1 = 0.f, ai0 = 0.f, ai1 = 0.f;
    #pragma unroll
    for (int k = 0; k < D; k++) {
        float uk = su[w][k];
        float ik = si[w][k];
        au0 += ws_u[k * D + lane]      * uk;
        au1 += ws_u[k * D + lane + 32] * uk;
        ai0 += ws_i[k * D + lane]      * ik;
        ai1 += ws_i[k * D + lane + 32] * ik;
    }

    // softmax over the 64 ue values (warp-wide reductions)
    float m = fmaxf(au0, au1);
    #pragma unroll
    for (int off = 16; off > 0; off >>= 1)
        m = fmaxf(m, __shfl_xor_sync(0xffffffffu, m, off));
    float ex0 = expf(au0 - m);
    float ex1 = expf(au1 - m);
    float ssum = ex0 + ex1;
    float tdot = ex0 * sigmoidf_(ai0) + ex1 * sigmoidf_(ai1);
    #pragma unroll
    for (int off = 16; off > 0; off >>= 1) {
        ssum += __shfl_xor_sync(0xffffffffu, ssum, off);
        tdot += __shfl_xor_sync(0xffffffffu, tdot, off);
    }

    if (lane == 0) {
        float xe = (xij[s] > 0) ? xij_emb1[item] : xij_emb0[item];
        out[s] = (1.0f - HYPER_X) * (tdot / ssum) + HYPER_X * sigmoidf_(xe);
    }
}

// ---------------------------------------------------------------------------
// kernel_launch
// inputs: 0 emb_user, 1 emb_item, 2 w_user, 3 w_item, 4 xij_emb1, 5 xij_emb0,
//         6 g_val, 7 g_row, 8 g_col, 9 users, 10 items, 11 xij
// ---------------------------------------------------------------------------
extern "C" void kernel_launch(void* const* d_in, const int* in_sizes, int n_in,
                              void* d_out, int out_size) {
    const float* emb_user = (const float*)d_in[0];
    const float* emb_item = (const float*)d_in[1];
    const float* w_user   = (const float*)d_in[2];
    const float* w_item   = (const float*)d_in[3];
    const float* xij_emb1 = (const float*)d_in[4];
    const float* xij_emb0 = (const float*)d_in[5];
    const float* g_val    = (const float*)d_in[6];
    const int*   g_row    = (const int*)d_in[7];
    const int*   g_col    = (const int*)d_in[8];
    const int*   users    = (const int*)d_in[9];
    const int*   items    = (const int*)d_in[10];
    const int*   xij      = (const int*)d_in[11];
    float*       out      = (float*)d_out;

    const int nnz = in_sizes[6];
    const int B   = in_sizes[9];

    float *e0, *e1, *e2, *e3;
    cudaGetSymbolAddress((void**)&e0, g_e0);
    cudaGetSymbolAddress((void**)&e1, g_e1);
    cudaGetSymbolAddress((void**)&e2, g_e2);
    cudaGetSymbolAddress((void**)&e3, g_e3);

    // init: copy embeddings into e0, zero e1..e3
    init_kernel<<<2048, 256>>>((const float4*)emb_user, (const float4*)emb_item);

    // SpMM chain: e1 = G e0 ; e2 = G e1 ; e3 = G e2
    const int threads = 256;
    const int edges_per_block = (threads / 32) * 2;   // 16 edges/block
    const int blocks = (nnz + edges_per_block - 1) / edges_per_block;
    spmm_kernel<<<blocks, threads>>>((const float4*)e0, e1, g_row, g_col, g_val, nnz);
    spmm_kernel<<<blocks, threads>>>((const float4*)e1, e2, g_row, g_col, g_val, nnz);
    spmm_kernel<<<blocks, threads>>>((const float4*)e2, e3, g_row, g_col, g_val, nnz);

    // epilogue
    const int eblocks = (B + SAMPLES_PER_BLOCK - 1) / SAMPLES_PER_BLOCK;
    epilogue_kernel<<<eblocks, 256>>>(w_user, w_item, xij_emb1, xij_emb0,
                                      users, items, xij, out, B);
}

// round 2
// speedup vs baseline: 1.6837x; 1.6837x over previous
#include <cuda_runtime.h>

#define N_USERS 100000
#define N_ITEMS 50000
#define N_TOTAL (N_USERS + N_ITEMS)
#define D 64
#define D2 (D / 2)
#define HYPER_X 0.5f
#define MAX_NNZ 2000000
#define SCAN_BLK 1024
#define SCAN_NB ((N_TOTAL + SCAN_BLK - 1) / SCAN_BLK)   // 147

// Feature buffers: e0 (input concat), e1..e3 (per-layer outputs)
__device__ float g_e0[N_TOTAL * D];
__device__ float g_e1[N_TOTAL * D];
__device__ float g_e2[N_TOTAL * D];
__device__ float g_e3[N_TOTAL * D];

// CSR scratch
__device__ int  g_deg[N_TOTAL];
__device__ int  g_offs[N_TOTAL + 1];
__device__ int  g_cursor[N_TOTAL];
__device__ int  g_blocksum[SCAN_NB];
__device__ int2 g_csr[MAX_NNZ];          // {col, float_as_int(val)}

// ---------------------------------------------------------------------------
// init: e0 = concat(emb_user, emb_item); deg = 0
// ---------------------------------------------------------------------------
__global__ void init_kernel(const float4* __restrict__ eu,
                            const float4* __restrict__ ei) {
    const int total = N_TOTAL * (D / 4);
    float4* b0 = reinterpret_cast<float4*>(g_e0);
    for (int i = blockIdx.x * blockDim.x + threadIdx.x; i < total;
         i += gridDim.x * blockDim.x) {
        b0[i] = (i < N_USERS * (D / 4)) ? eu[i] : ei[i - N_USERS * (D / 4)];
    }
    for (int i = blockIdx.x * blockDim.x + threadIdx.x; i < N_TOTAL;
         i += gridDim.x * blockDim.x) {
        g_deg[i] = 0;
    }
}

// ---------------------------------------------------------------------------
// CSR build
// ---------------------------------------------------------------------------
__global__ void hist_kernel(const int* __restrict__ row, int nnz) {
    int e = blockIdx.x * blockDim.x + threadIdx.x;
    if (e < nnz) atomicAdd(&g_deg[row[e]], 1);
}

// block-level exclusive scan helper (blockDim.x == 1024)
__device__ __forceinline__ int block_exscan(int v, int* sh) {
    int lane = threadIdx.x & 31, wid = threadIdx.x >> 5;
    int incl = v;
    #pragma unroll
    for (int o = 1; o < 32; o <<= 1) {
        int n = __shfl_up_sync(0xffffffffu, incl, o);
        if (lane >= o) incl += n;
    }
    if (lane == 31) sh[wid] = incl;
    __syncthreads();
    if (wid == 0) {
        int w = sh[lane];
        #pragma unroll
        for (int o = 1; o < 32; o <<= 1) {
            int n = __shfl_up_sync(0xffffffffu, w, o);
            if (lane >= o) w += n;
        }
        sh[lane] = w;
    }
    __syncthreads();
    int warpoff = (wid > 0) ? sh[wid - 1] : 0;
    return warpoff + incl - v;
}

__global__ void scan_partial_kernel() {     // grid = SCAN_NB, block = 1024
    __shared__ int sh[32];
    int i = blockIdx.x * SCAN_BLK + threadIdx.x;
    int v = (i < N_TOTAL) ? g_deg[i] : 0;
    int ex = block_exscan(v, sh);
    if (threadIdx.x == SCAN_BLK - 1) g_blocksum[blockIdx.x] = ex + v;
}

__global__ void scan_top_kernel() {         // single block, 256 threads
    __shared__ int sh[256];
    int t = threadIdx.x;
    int v = (t < SCAN_NB) ? g_blocksum[t] : 0;
    sh[t] = v;
    __syncthreads();
    int acc = v;
    for (int o = 1; o < 256; o <<= 1) {
        int n = (t >= o) ? sh[t - o] : 0;
        __syncthreads();
        acc += n;
        sh[t] = acc;
        __syncthreads();
    }
    if (t < SCAN_NB) g_blocksum[t] = acc - v;   // exclusive
}

__global__ void scan_final_kernel() {       // grid = SCAN_NB, block = 1024
    __shared__ int sh[32];
    int i = blockIdx.x * SCAN_BLK + threadIdx.x;
    int v = (i < N_TOTAL) ? g_deg[i] : 0;
    int ex = block_exscan(v, sh) + g_blocksum[blockIdx.x];
    if (i < N_TOTAL) {
        g_offs[i]   = ex;
        g_cursor[i] = ex;
        if (i == N_TOTAL - 1) g_offs[N_TOTAL] = ex + v;
    }
}

__global__ void fill_kernel(const int* __restrict__ row,
                            const int* __restrict__ col,
                            const float* __restrict__ val, int nnz) {
    int e = blockIdx.x * blockDim.x + threadIdx.x;
    if (e < nnz) {
        int pos = atomicAdd(&g_cursor[row[e]], 1);
        g_csr[pos] = make_int2(col[e], __float_as_int(val[e]));
    }
}

// ---------------------------------------------------------------------------
// SpMM (CSR, gather form): one warp per output row, float2 per lane.
// y[r] = sum_{j in row r} val_j * x[col_j]
// ---------------------------------------------------------------------------
__global__ void spmm_csr_kernel(const float2* __restrict__ x,
                                float2* __restrict__ y) {
    const int lane = threadIdx.x & 31;
    const int r = (blockIdx.x * blockDim.x + threadIdx.x) >> 5;
    if (r >= N_TOTAL) return;

    const int beg = g_offs[r];
    const int end = g_offs[r + 1];

    float ax = 0.f, ay = 0.f;
    int j = beg;
    for (; j + 1 < end; j += 2) {
        int2 m0 = g_csr[j];
        int2 m1 = g_csr[j + 1];
        float2 x0 = __ldg(&x[(long)m0.x * D2 + lane]);
        float2 x1 = __ldg(&x[(long)m1.x * D2 + lane]);
        float v0 = __int_as_float(m0.y);
        float v1 = __int_as_float(m1.y);
        ax += v0 * x0.x; ay += v0 * x0.y;
        ax += v1 * x1.x; ay += v1 * x1.y;
    }
    if (j < end) {
        int2 m = g_csr[j];
        float2 xv = __ldg(&x[(long)m.x * D2 + lane]);
        float v = __int_as_float(m.y);
        ax += v * xv.x; ay += v * xv.y;
    }
    y[(long)r * D2 + lane] = make_float2(ax, ay);
}

// ---------------------------------------------------------------------------
// Epilogue (unchanged from R1): 32 threads/sample, 8 samples/block
// ---------------------------------------------------------------------------
#define SAMPLES_PER_BLOCK 8

__device__ __forceinline__ float sigmoidf_(float x) {
    return 1.0f / (1.0f + expf(-x));
}

__global__ void epilogue_kernel(const float* __restrict__ w_user,
                                const float* __restrict__ w_item,
                                const float* __restrict__ xij_emb1,
                                const float* __restrict__ xij_emb0,
                                const int* __restrict__ users,
                                const int* __restrict__ items,
                                const int* __restrict__ xij,
                                float* __restrict__ out,
                                int B) {
    __shared__ float ws_u[D * D];                 // transposed
    __shared__ float ws_i[D * D];
    __shared__ float su[SAMPLES_PER_BLOCK][D];
    __shared__ float si[SAMPLES_PER_BLOCK][D];

    const int tid = threadIdx.x;
    for (int idx = tid; idx < D * D; idx += blockDim.x) {
        int d = idx >> 6, k = idx & 63;
        ws_u[k * D + d] = w_user[idx];
        ws_i[k * D + d] = w_item[idx];
    }

    const int w    = tid >> 5;
    const int lane = tid & 31;
    const int s    = blockIdx.x * SAMPLES_PER_BLOCK + w;

    int item = 0;
    if (s < B) {
        int urow = users[s];
        item = items[s];
        int irow = N_USERS + item;
        #pragma unroll
        for (int t = 0; t < 2; t++) {
            int j = lane + t * 32;
            long uo = (long)urow * D + j;
            long io = (long)irow * D + j;
            su[w][j] = 0.25f * (g_e0[uo] + g_e1[uo] + g_e2[uo] + g_e3[uo]);
            si[w][j] = 0.25f * (g_e0[io] + g_e1[io] + g_e2[io] + g_e3[io]);
        }
    }
    __syncthreads();
    if (s >= B) return;

    float au0 = 0.f, au1 = 0.f, ai0 = 0.f, ai1 = 0.f;
    #pragma unroll
    for (int k = 0; k < D; k++) {
        float uk = su[w][k];
        float ik = si[w][k];
        au0 += ws_u[k * D + lane]      * uk;
        au1 += ws_u[k * D + lane + 32] * uk;
        ai0 += ws_i[k * D + lane]      * ik;
        ai1 += ws_i[k * D + lane + 32] * ik;
    }

    float m = fmaxf(au0, au1);
    #pragma unroll
    for (int off = 16; off > 0; off >>= 1)
        m = fmaxf(m, __shfl_xor_sync(0xffffffffu, m, off));
    float ex0 = expf(au0 - m);
    float ex1 = expf(au1 - m);
    float ssum = ex0 + ex1;
    float tdot = ex0 * sigmoidf_(ai0) + ex1 * sigmoidf_(ai1);
    #pragma unroll
    for (int off = 16; off > 0; off >>= 1) {
        ssum += __shfl_xor_sync(0xffffffffu, ssum, off);
        tdot += __shfl_xor_sync(0xffffffffu, tdot, off);
    }

    if (lane == 0) {
        float xe = (xij[s] > 0) ? xij_emb1[item] : xij_emb0[item];
        out[s] = (1.0f - HYPER_X) * (tdot / ssum) + HYPER_X * sigmoidf_(xe);
    }
}

// ---------------------------------------------------------------------------
// kernel_launch
// ---------------------------------------------------------------------------
extern "C" void kernel_launch(void* const* d_in, const int* in_sizes, int n_in,
                              void* d_out, int out_size) {
    const float* emb_user = (const float*)d_in[0];
    const float* emb_item = (const float*)d_in[1];
    const float* w_user   = (const float*)d_in[2];
    const float* w_item   = (const float*)d_in[3];
    const float* xij_emb1 = (const float*)d_in[4];
    const float* xij_emb0 = (const float*)d_in[5];
    const float* g_val    = (const float*)d_in[6];
    const int*   g_row    = (const int*)d_in[7];
    const int*   g_col    = (const int*)d_in[8];
    const int*   users    = (const int*)d_in[9];
    const int*   items    = (const int*)d_in[10];
    const int*   xij      = (const int*)d_in[11];
    float*       out      = (float*)d_out;

    const int nnz = in_sizes[6];
    const int B   = in_sizes[9];

    float *e0, *e1, *e2, *e3;
    cudaGetSymbolAddress((void**)&e0, g_e0);
    cudaGetSymbolAddress((void**)&e1, g_e1);
    cudaGetSymbolAddress((void**)&e2, g_e2);
    cudaGetSymbolAddress((void**)&e3, g_e3);

    // init + CSR build
    init_kernel<<<2048, 256>>>((const float4*)emb_user, (const float4*)emb_item);
    hist_kernel<<<(nnz + 255) / 256, 256>>>(g_row, nnz);
    scan_partial_kernel<<<SCAN_NB, SCAN_BLK>>>();
    scan_top_kernel<<<1, 256>>>();
    scan_final_kernel<<<SCAN_NB, SCAN_BLK>>>();
    fill_kernel<<<(nnz + 255) / 256, 256>>>(g_row, g_col, g_val, nnz);

    // SpMM chain (gather form)
    const int warps_per_block = 8;                 // 256 threads
    const int sblocks = (N_TOTAL + warps_per_block - 1) / warps_per_block;
    spmm_csr_kernel<<<sblocks, 256>>>((const float2*)e0, (float2*)e1);
    spmm_csr_kernel<<<sblocks, 256>>>((const float2*)e1, (float2*)e2);
    spmm_csr_kernel<<<sblocks, 256>>>((const float2*)e2, (float2*)e3);

    // epilogue
    const int eblocks = (B + SAMPLES_PER_BLOCK - 1) / SAMPLES_PER_BLOCK;
    epilogue_kernel<<<eblocks, 256>>>(w_user, w_item, xij_emb1, xij_emb0,
                                      users, items, xij, out, B);
}

// round 3
// speedup vs baseline: 1.8173x; 1.0794x over previous
#include <cuda_runtime.h>

#define N_USERS 100000
#define N_ITEMS 50000
#define N_TOTAL (N_USERS + N_ITEMS)
#define D 64
#define D2 (D / 2)
#define HYPER_X 0.5f
#define MAX_NNZ 2000000
#define MAX_SAMPLED 32768
#define SCAN_BLK 1024
#define SCAN_NB ((N_TOTAL + SCAN_BLK - 1) / SCAN_BLK)   // 147

// Feature buffers (e0 eliminated: layer-0 is read straight from the inputs)
__device__ float g_e1[N_TOTAL * D];
__device__ float g_e2[N_TOTAL * D];
__device__ float g_e3[N_TOTAL * D];

// CSR scratch
__device__ int  g_deg[N_TOTAL];
__device__ int  g_offs[N_TOTAL + 1];
__device__ int  g_cursor[N_TOTAL];
__device__ int  g_blocksum[SCAN_NB];
__device__ int2 g_csr[MAX_NNZ];          // {col, float_as_int(val)}

// sampled-row dedup for masked layer 3
__device__ int g_flag[N_TOTAL];
__device__ int g_rowlist[MAX_SAMPLED];
__device__ int g_rowcount;

// ---------------------------------------------------------------------------
// zero: deg, flag, rowcount
// ---------------------------------------------------------------------------
__global__ void zero_kernel() {
    int i = blockIdx.x * blockDim.x + threadIdx.x;
    if (i < N_TOTAL) { g_deg[i] = 0; g_flag[i] = 0; }
    if (i == 0) g_rowcount = 0;
}

// ---------------------------------------------------------------------------
// mark sampled rows (dedup via flag) into g_rowlist
// ---------------------------------------------------------------------------
__global__ void mark_kernel(const int* __restrict__ users,
                            const int* __restrict__ items, int B) {
    int s = blockIdx.x * blockDim.x + threadIdx.x;
    if (s >= B) return;
    int u = users[s];
    if (atomicExch(&g_flag[u], 1) == 0) {
        int p = atomicAdd(&g_rowcount, 1);
        g_rowlist[p] = u;
    }
    int it = N_USERS + items[s];
    if (atomicExch(&g_flag[it], 1) == 0) {
        int p = atomicAdd(&g_rowcount, 1);
        g_rowlist[p] = it;
    }
}

// ---------------------------------------------------------------------------
// CSR build
// ---------------------------------------------------------------------------
__global__ void hist_kernel(const int* __restrict__ row, int nnz) {
    int e = blockIdx.x * blockDim.x + threadIdx.x;
    if (e < nnz) atomicAdd(&g_deg[row[e]], 1);
}

__device__ __forceinline__ int block_exscan(int v, int* sh) {
    int lane = threadIdx.x & 31, wid = threadIdx.x >> 5;
    int incl = v;
    #pragma unroll
    for (int o = 1; o < 32; o <<= 1) {
        int n = __shfl_up_sync(0xffffffffu, incl, o);
        if (lane >= o) incl += n;
    }
    if (lane == 31) sh[wid] = incl;
    __syncthreads();
    if (wid == 0) {
        int w = sh[lane];
        #pragma unroll
        for (int o = 1; o < 32; o <<= 1) {
            int n = __shfl_up_sync(0xffffffffu, w, o);
            if (lane >= o) w += n;
        }
        sh[lane] = w;
    }
    __syncthreads();
    int warpoff = (wid > 0) ? sh[wid - 1] : 0;
    return warpoff + incl - v;
}

__global__ void scan_partial_kernel() {     // grid = SCAN_NB, block = 1024
    __shared__ int sh[32];
    int i = blockIdx.x * SCAN_BLK + threadIdx.x;
    int v = (i < N_TOTAL) ? g_deg[i] : 0;
    int ex = block_exscan(v, sh);
    if (threadIdx.x == SCAN_BLK - 1) g_blocksum[blockIdx.x] = ex + v;
}

// scan_final with inlined top-level: each block sums blocksum[0..bid)
__global__ void scan_final_kernel() {       // grid = SCAN_NB, block = 1024
    __shared__ int sh[32];
    __shared__ int base_sh;
    if (threadIdx.x == 0) base_sh = 0;
    __syncthreads();
    int t = threadIdx.x;
    if (t < blockIdx.x) atomicAdd(&base_sh, g_blocksum[t]);
    __syncthreads();
    int i = blockIdx.x * SCAN_BLK + t;
    int v = (i < N_TOTAL) ? g_deg[i] : 0;
    int ex = block_exscan(v, sh) + base_sh;
    if (i < N_TOTAL) {
        g_offs[i]   = ex;
        g_cursor[i] = ex;
        if (i == N_TOTAL - 1) g_offs[N_TOTAL] = ex + v;
    }
}

__global__ void fill_kernel(const int* __restrict__ row,
                            const int* __restrict__ col,
                            const float* __restrict__ val, int nnz) {
    int e = blockIdx.x * blockDim.x + threadIdx.x;
    if (e < nnz) {
        int pos = atomicAdd(&g_cursor[row[e]], 1);
        g_csr[pos] = make_int2(col[e], __float_as_int(val[e]));
    }
}

// ---------------------------------------------------------------------------
// SpMM layer 1: gathers straight from the embedding inputs (no e0 buffer)
// ---------------------------------------------------------------------------
__global__ void spmm_l1_kernel(const float2* __restrict__ eu,
                               const float2* __restrict__ ei,
                               float2* __restrict__ y) {
    const int lane = threadIdx.x & 31;
    const int r = (blockIdx.x * blockDim.x + threadIdx.x) >> 5;
    if (r >= N_TOTAL) return;

    const int beg = g_offs[r];
    const int end = g_offs[r + 1];

    float ax = 0.f, ay = 0.f;
    int j = beg;
    for (; j + 1 < end; j += 2) {
        int2 m0 = g_csr[j];
        int2 m1 = g_csr[j + 1];
        const float2* b0 = (m0.x < N_USERS) ? (eu + (long)m0.x * D2)
                                            : (ei + (long)(m0.x - N_USERS) * D2);
        const float2* b1 = (m1.x < N_USERS) ? (eu + (long)m1.x * D2)
                                            : (ei + (long)(m1.x - N_USERS) * D2);
        float2 x0 = __ldg(&b0[lane]);
        float2 x1 = __ldg(&b1[lane]);
        float v0 = __int_as_float(m0.y);
        float v1 = __int_as_float(m1.y);
        ax += v0 * x0.x; ay += v0 * x0.y;
        ax += v1 * x1.x; ay += v1 * x1.y;
    }
    if (j < end) {
        int2 m = g_csr[j];
        const float2* b = (m.x < N_USERS) ? (eu + (long)m.x * D2)
                                          : (ei + (long)(m.x - N_USERS) * D2);
        float2 xv = __ldg(&b[lane]);
        float v = __int_as_float(m.y);
        ax += v * xv.x; ay += v * xv.y;
    }
    y[(long)r * D2 + lane] = make_float2(ax, ay);
}

// ---------------------------------------------------------------------------
// SpMM layer 2: full, e1 -> e2
// ---------------------------------------------------------------------------
__global__ void spmm_csr_kernel(const float2* __restrict__ x,
                                float2* __restrict__ y) {
    const int lane = threadIdx.x & 31;
    const int r = (blockIdx.x * blockDim.x + threadIdx.x) >> 5;
    if (r >= N_TOTAL) return;

    const int beg = g_offs[r];
    const int end = g_offs[r + 1];

    float ax = 0.f, ay = 0.f;
    int j = beg;
    for (; j + 1 < end; j += 2) {
        int2 m0 = g_csr[j];
        int2 m1 = g_csr[j + 1];
        float2 x0 = __ldg(&x[(long)m0.x * D2 + lane]);
        float2 x1 = __ldg(&x[(long)m1.x * D2 + lane]);
        float v0 = __int_as_float(m0.y);
        float v1 = __int_as_float(m1.y);
        ax += v0 * x0.x; ay += v0 * x0.y;
        ax += v1 * x1.x; ay += v1 * x1.y;
    }
    if (j < end) {
        int2 m = g_csr[j];
        float2 xv = __ldg(&x[(long)m.x * D2 + lane]);
        float v = __int_as_float(m.y);
        ax += v * xv.x; ay += v * xv.y;
    }
    y[(long)r * D2 + lane] = make_float2(ax, ay);
}

// ---------------------------------------------------------------------------
// SpMM layer 3: only sampled rows (g_rowlist), e2 -> e3
// ---------------------------------------------------------------------------
__global__ void spmm_list_kernel(const float2* __restrict__ x,
                                 float2* __restrict__ y) {
    const int lane = threadIdx.x & 31;
    const int idx = (blockIdx.x * blockDim.x + threadIdx.x) >> 5;
    if (idx >= g_rowcount) return;
    const int r = g_rowlist[idx];

    const int beg = g_offs[r];
    const int end = g_offs[r + 1];

    float ax = 0.f, ay = 0.f;
    int j = beg;
    for (; j + 1 < end; j += 2) {
        int2 m0 = g_csr[j];
        int2 m1 = g_csr[j + 1];
        float2 x0 = __ldg(&x[(long)m0.x * D2 + lane]);
        float2 x1 = __ldg(&x[(long)m1.x * D2 + lane]);
        float v0 = __int_as_float(m0.y);
        float v1 = __int_as_float(m1.y);
        ax += v0 * x0.x; ay += v0 * x0.y;
        ax += v1 * x1.x; ay += v1 * x1.y;
    }
    if (j < end) {
        int2 m = g_csr[j];
        float2 xv = __ldg(&x[(long)m.x * D2 + lane]);
        float v = __int_as_float(m.y);
        ax += v * xv.x; ay += v * xv.y;
    }
    y[(long)r * D2 + lane] = make_float2(ax, ay);
}

// ---------------------------------------------------------------------------
// Epilogue: 32 threads/sample, 8 samples/block. e0 read from inputs.
// ---------------------------------------------------------------------------
#define SAMPLES_PER_BLOCK 8

__device__ __forceinline__ float sigmoidf_(float x) {
    return 1.0f / (1.0f + expf(-x));
}

__global__ void epilogue_kernel(const float* __restrict__ emb_user,
                                const float* __restrict__ emb_item,
                                const float* __restrict__ w_user,
                                const float* __restrict__ w_item,
                                const float* __restrict__ xij_emb1,
                                const float* __restrict__ xij_emb0,
                                const int* __restrict__ users,
                                const int* __restrict__ items,
                                const int* __restrict__ xij,
                                float* __restrict__ out,
                                int B) {
    __shared__ float ws_u[D * D];                 // transposed
    __shared__ float ws_i[D * D];
    __shared__ float su[SAMPLES_PER_BLOCK][D];
    __shared__ float si[SAMPLES_PER_BLOCK][D];

    const int tid = threadIdx.x;
    for (int idx = tid; idx < D * D; idx += blockDim.x) {
        int d = idx >> 6, k = idx & 63;
        ws_u[k * D + d] = w_user[idx];
        ws_i[k * D + d] = w_item[idx];
    }

    const int w    = tid >> 5;
    const int lane = tid & 31;
    const int s    = blockIdx.x * SAMPLES_PER_BLOCK + w;

    int item = 0;
    if (s < B) {
        int urow = users[s];
        item = items[s];
        int irow = N_USERS + item;
        #pragma unroll
        for (int t = 0; t < 2; t++) {
            int j = lane + t * 32;
            long uo = (long)urow * D + j;
            long io = (long)irow * D + j;
            su[w][j] = 0.25f * (emb_user[uo] + g_e1[uo] + g_e2[uo] + g_e3[uo]);
            si[w][j] = 0.25f * (emb_item[(long)item * D + j]
                                + g_e1[io] + g_e2[io] + g_e3[io]);
        }
    }
    __syncthreads();
    if (s >= B) return;

    float au0 = 0.f, au1 = 0.f, ai0 = 0.f, ai1 = 0.f;
    #pragma unroll
    for (int k = 0; k < D; k++) {
        float uk = su[w][k];
        float ik = si[w][k];
        au0 += ws_u[k * D + lane]      * uk;
        au1 += ws_u[k * D + lane + 32] * uk;
        ai0 += ws_i[k * D + lane]      * ik;
        ai1 += ws_i[k * D + lane + 32] * ik;
    }

    float m = fmaxf(au0, au1);
    #pragma unroll
    for (int off = 16; off > 0; off >>= 1)
        m = fmaxf(m, __shfl_xor_sync(0xffffffffu, m, off));
    float ex0 = expf(au0 - m);
    float ex1 = expf(au1 - m);
    float ssum = ex0 + ex1;
    float tdot = ex0 * sigmoidf_(ai0) + ex1 * sigmoidf_(ai1);
    #pragma unroll
    for (int off = 16; off > 0; off >>= 1) {
        ssum += __shfl_xor_sync(0xffffffffu, ssum, off);
        tdot += __shfl_xor_sync(0xffffffffu, tdot, off);
    }

    if (lane == 0) {
        float xe = (xij[s] > 0) ? xij_emb1[item] : xij_emb0[item];
        out[s] = (1.0f - HYPER_X) * (tdot / ssum) + HYPER_X * sigmoidf_(xe);
    }
}

// ---------------------------------------------------------------------------
// kernel_launch
// ---------------------------------------------------------------------------
extern "C" void kernel_launch(void* const* d_in, const int* in_sizes, int n_in,
                              void* d_out, int out_size) {
    const float* emb_user = (const float*)d_in[0];
    const float* emb_item = (const float*)d_in[1];
    const float* w_user   = (const float*)d_in[2];
    const float* w_item   = (const float*)d_in[3];
    const float* xij_emb1 = (const float*)d_in[4];
    const float* xij_emb0 = (const float*)d_in[5];
    const float* g_val    = (const float*)d_in[6];
    const int*   g_row    = (const int*)d_in[7];
    const int*   g_col    = (const int*)d_in[8];
    const int*   users    = (const int*)d_in[9];
    const int*   items    = (const int*)d_in[10];
    const int*   xij      = (const int*)d_in[11];
    float*       out      = (float*)d_out;

    const int nnz = in_sizes[6];
    const int B   = in_sizes[9];

    float *e1, *e2, *e3;
    cudaGetSymbolAddress((void**)&e1, g_e1);
    cudaGetSymbolAddress((void**)&e2, g_e2);
    cudaGetSymbolAddress((void**)&e3, g_e3);

    // zero + mark sampled rows + CSR build
    zero_kernel<<<(N_TOTAL + 255) / 256, 256>>>();
    mark_kernel<<<(B + 255) / 256, 256>>>(users, items, B);
    hist_kernel<<<(nnz + 255) / 256, 256>>>(g_row, nnz);
    scan_partial_kernel<<<SCAN_NB, SCAN_BLK>>>();
    scan_final_kernel<<<SCAN_NB, SCAN_BLK>>>();
    fill_kernel<<<(nnz + 255) / 256, 256>>>(g_row, g_col, g_val, nnz);

    // SpMM chain
    const int warps_per_block = 8;                 // 256 threads
    const int sblocks = (N_TOTAL + warps_per_block - 1) / warps_per_block;
    spmm_l1_kernel<<<sblocks, 256>>>((const float2*)emb_user,
                                     (const float2*)emb_item, (float2*)e1);
    spmm_csr_kernel<<<sblocks, 256>>>((const float2*)e1, (float2*)e2);
    const int lblocks = (MAX_SAMPLED + warps_per_block - 1) / warps_per_block;
    spmm_list_kernel<<<lblocks, 256>>>((const float2*)e2, (float2*)e3);

    // epilogue
    const int eblocks = (B + SAMPLES_PER_BLOCK - 1) / SAMPLES_PER_BLOCK;
    epilogue_kernel<<<eblocks, 256>>>(emb_user, emb_item, w_user, w_item,
                                      xij_emb1, xij_emb0, users, items, xij,
                                      out, B);
}